// round 5
// baseline (speedup 1.0000x reference)
#include <cuda_runtime.h>

#define NN 50000
#define EE 1600000
#define FULL 0xffffffffu

typedef unsigned long long u64t;

__device__ __forceinline__ u64t pk(float lo, float hi) {
    u64t r; asm("mov.b64 %0,{%1,%2};" : "=l"(r) : "f"(lo), "f"(hi)); return r;
}
__device__ __forceinline__ void upk(u64t v, float& lo, float& hi) {
    asm("mov.b64 {%0,%1},%2;" : "=f"(lo), "=f"(hi) : "l"(v));
}
__device__ __forceinline__ u64t f2fma(u64t a, u64t b, u64t c) {
    u64t d; asm("fma.rn.f32x2 %0,%1,%2,%3;" : "=l"(d) : "l"(a), "l"(b), "l"(c)); return d;
}
// streaming (evict-first) 16B load — keeps ef out of L2 so node tables stay resident
__device__ __forceinline__ ulonglong2 ldcs2(const ulonglong2* p) {
    ulonglong2 r;
    asm("ld.global.cs.v2.u64 {%0,%1},[%2];" : "=l"(r.x), "=l"(r.y) : "l"(p));
    return r;
}

// ---------------- scratch (device globals; no allocation allowed) ----------
__device__ float g_q1[NN*128];
__device__ float g_k1[NN*128];
__device__ float g_v1[NN*128];
__device__ float g_h [NN*128];
__device__ float g_t1[NN*256];
__device__ float g_q2[NN*64];
__device__ float g_k2[NN*64];
__device__ float g_v2[NN*64];
__device__ float g_s2[NN*64];
__device__ float g_t2[NN*64];
__device__ int   g_cnt[NN];
__device__ int   g_rowptr[NN+1];
__device__ int   g_woff[NN];
__device__ int2  g_edges[EE];

// ---------------- CSR build ------------------------------------------------
__global__ void k_zero_cnt() {
    int i = blockIdx.x*blockDim.x + threadIdx.x;
    if (i < NN) g_cnt[i] = 0;
}

__global__ void k_hist(const int* __restrict__ dst) {
    int e = blockIdx.x*blockDim.x + threadIdx.x;
    if (e < EE) atomicAdd(&g_cnt[dst[e]], 1);
}

__global__ void k_scan() {
    __shared__ int s[1024];
    __shared__ int carry;
    if (threadIdx.x == 0) carry = 0;
    __syncthreads();
    for (int base = 0; base < NN; base += 1024) {
        int i = base + threadIdx.x;
        int v = (i < NN) ? g_cnt[i] : 0;
        s[threadIdx.x] = v;
        __syncthreads();
        for (int off = 1; off < 1024; off <<= 1) {
            int t = (threadIdx.x >= off) ? s[threadIdx.x - off] : 0;
            __syncthreads();
            s[threadIdx.x] += t;
            __syncthreads();
        }
        int excl = s[threadIdx.x] - v;
        if (i < NN) { g_rowptr[i] = carry + excl; g_woff[i] = carry + excl; }
        int tot = s[1023];
        __syncthreads();
        if (threadIdx.x == 0) carry += tot;
        __syncthreads();
    }
    if (threadIdx.x == 0) g_rowptr[NN] = carry;
}

__global__ void k_scatter(const int* __restrict__ src, const int* __restrict__ dst) {
    int e = blockIdx.x*blockDim.x + threadIdx.x;
    if (e < EE) {
        int d = dst[e];
        int p = atomicAdd(&g_woff[d], 1);
        g_edges[p] = make_int2(src[e], e);
    }
}

// ---------------- node linear layers: register-tiled, packed f32x2 ---------
// layer1: 64 nodes x 128 cols per block; thread: 4 nodes x 8 cols
__global__ void __launch_bounds__(256) k_node1(const float* __restrict__ x,
    const float* __restrict__ Wq, const float* __restrict__ bq,
    const float* __restrict__ Wk, const float* __restrict__ bk,
    const float* __restrict__ Wv, const float* __restrict__ bv,
    const float* __restrict__ Ws, const float* __restrict__ bs)
{
    const int CIN = 128, COUT = 128;
    int mat = blockIdx.y;
    const float* W = (mat==0)?Wq:((mat==1)?Wk:((mat==2)?Wv:Ws));
    const float* b = (mat==0)?bq:((mat==1)?bk:((mat==2)?bv:bs));
    float* o = (mat==0)?g_q1:((mat==1)?g_k1:((mat==2)?g_v1:g_h));
    int n0 = blockIdx.x * 64;

    __shared__ float xs2[32][128];  // duplicated pairs {v,v} per node, 16KB
    __shared__ float ws[32][128];   // W[k][col], 16KB

    int tid = threadIdx.x;
    int tx = tid & 15, ty = tid >> 4;
    int col0 = tx*8;
    int nb = ty*4;

    u64t acc[4][4];
    #pragma unroll
    for (int cp = 0; cp < 4; cp++) {
        u64t bp = pk(b[col0+2*cp], b[col0+2*cp+1]);
        acc[0][cp] = bp; acc[1][cp] = bp; acc[2][cp] = bp; acc[3][cp] = bp;
    }

    for (int kc = 0; kc < CIN; kc += 32) {
        if (kc) __syncthreads();
        #pragma unroll
        for (int i = tid; i < 64*32; i += 256) {
            int nn = i >> 5, kk = i & 31;
            int row = n0 + nn;
            float v = (row < NN) ? x[(size_t)row*CIN + kc + kk] : 0.f;
            xs2[kk][2*nn] = v; xs2[kk][2*nn+1] = v;
        }
        #pragma unroll
        for (int i = tid; i < 32*COUT; i += 256) {
            int kk = i >> 7, c = i & 127;
            ws[kk][c] = W[(size_t)(kc+kk)*COUT + c];
        }
        __syncthreads();
        #pragma unroll 4
        for (int kk = 0; kk < 32; kk++) {
            const u64t* xr = (const u64t*)&xs2[kk][2*nb];
            u64t xp0 = xr[0], xp1 = xr[1], xp2 = xr[2], xp3 = xr[3];
            const u64t* wr = (const u64t*)&ws[kk][col0];
            u64t w0 = wr[0], w1 = wr[1], w2 = wr[2], w3 = wr[3];
            acc[0][0]=f2fma(xp0,w0,acc[0][0]); acc[0][1]=f2fma(xp0,w1,acc[0][1]);
            acc[0][2]=f2fma(xp0,w2,acc[0][2]); acc[0][3]=f2fma(xp0,w3,acc[0][3]);
            acc[1][0]=f2fma(xp1,w0,acc[1][0]); acc[1][1]=f2fma(xp1,w1,acc[1][1]);
            acc[1][2]=f2fma(xp1,w2,acc[1][2]); acc[1][3]=f2fma(xp1,w3,acc[1][3]);
            acc[2][0]=f2fma(xp2,w0,acc[2][0]); acc[2][1]=f2fma(xp2,w1,acc[2][1]);
            acc[2][2]=f2fma(xp2,w2,acc[2][2]); acc[2][3]=f2fma(xp2,w3,acc[2][3]);
            acc[3][0]=f2fma(xp3,w0,acc[3][0]); acc[3][1]=f2fma(xp3,w1,acc[3][1]);
            acc[3][2]=f2fma(xp3,w2,acc[3][2]); acc[3][3]=f2fma(xp3,w3,acc[3][3]);
        }
    }
    #pragma unroll
    for (int nn = 0; nn < 4; nn++) {
        int row = n0 + nb + nn;
        if (row < NN) {
            #pragma unroll
            for (int cp = 0; cp < 4; cp++) {
                float a0, a1; upk(acc[nn][cp], a0, a1);
                *(float2*)&o[(size_t)row*COUT + col0 + 2*cp] = make_float2(a0, a1);
            }
        }
    }
}

// layer2: 128 nodes x 64 cols per block; thread: 4 nodes x 8 cols
__global__ void __launch_bounds__(256) k_node2(
    const float* __restrict__ Wq, const float* __restrict__ bq,
    const float* __restrict__ Wk, const float* __restrict__ bk,
    const float* __restrict__ Wv, const float* __restrict__ bv,
    const float* __restrict__ Ws, const float* __restrict__ bs)
{
    const int CIN = 128, COUT = 64;
    int mat = blockIdx.y;
    const float* W = (mat==0)?Wq:((mat==1)?Wk:((mat==2)?Wv:Ws));
    const float* b = (mat==0)?bq:((mat==1)?bk:((mat==2)?bv:bs));
    float* o = (mat==0)?g_q2:((mat==1)?g_k2:((mat==2)?g_v2:g_s2));
    int n0 = blockIdx.x * 128;

    __shared__ float xs2[32][256];  // 32KB
    __shared__ float ws[32][64];    // 8KB

    int tid = threadIdx.x;
    int tx = tid & 7, ty = tid >> 3;
    int col0 = tx*8;
    int nb = ty*4;

    u64t acc[4][4];
    #pragma unroll
    for (int cp = 0; cp < 4; cp++) {
        u64t bp = pk(b[col0+2*cp], b[col0+2*cp+1]);
        acc[0][cp] = bp; acc[1][cp] = bp; acc[2][cp] = bp; acc[3][cp] = bp;
    }

    for (int kc = 0; kc < CIN; kc += 32) {
        if (kc) __syncthreads();
        #pragma unroll
        for (int i = tid; i < 128*32; i += 256) {
            int nn = i >> 5, kk = i & 31;
            int row = n0 + nn;
            float v = (row < NN) ? g_h[(size_t)row*CIN + kc + kk] : 0.f;
            xs2[kk][2*nn] = v; xs2[kk][2*nn+1] = v;
        }
        #pragma unroll
        for (int i = tid; i < 32*COUT; i += 256) {
            int kk = i >> 6, c = i & 63;
            ws[kk][c] = W[(size_t)(kc+kk)*COUT + c];
        }
        __syncthreads();
        #pragma unroll 4
        for (int kk = 0; kk < 32; kk++) {
            const u64t* xr = (const u64t*)&xs2[kk][2*nb];
            u64t xp0 = xr[0], xp1 = xr[1], xp2 = xr[2], xp3 = xr[3];
            const u64t* wr = (const u64t*)&ws[kk][col0];
            u64t w0 = wr[0], w1 = wr[1], w2 = wr[2], w3 = wr[3];
            acc[0][0]=f2fma(xp0,w0,acc[0][0]); acc[0][1]=f2fma(xp0,w1,acc[0][1]);
            acc[0][2]=f2fma(xp0,w2,acc[0][2]); acc[0][3]=f2fma(xp0,w3,acc[0][3]);
            acc[1][0]=f2fma(xp1,w0,acc[1][0]); acc[1][1]=f2fma(xp1,w1,acc[1][1]);
            acc[1][2]=f2fma(xp1,w2,acc[1][2]); acc[1][3]=f2fma(xp1,w3,acc[1][3]);
            acc[2][0]=f2fma(xp2,w0,acc[2][0]); acc[2][1]=f2fma(xp2,w1,acc[2][1]);
            acc[2][2]=f2fma(xp2,w2,acc[2][2]); acc[2][3]=f2fma(xp2,w3,acc[2][3]);
            acc[3][0]=f2fma(xp3,w0,acc[3][0]); acc[3][1]=f2fma(xp3,w1,acc[3][1]);
            acc[3][2]=f2fma(xp3,w2,acc[3][2]); acc[3][3]=f2fma(xp3,w3,acc[3][3]);
        }
    }
    #pragma unroll
    for (int nn = 0; nn < 4; nn++) {
        int row = n0 + nb + nn;
        if (row < NN) {
            #pragma unroll
            for (int cp = 0; cp < 4; cp++) {
                float a0, a1; upk(acc[nn][cp], a0, a1);
                *(float2*)&o[(size_t)row*COUT + col0 + 2*cp] = make_float2(a0, a1);
            }
        }
    }
}

// ---------------- t tables --------------------------------------------------
__global__ void k_t1(const float* __restrict__ We1) {
    int h = blockIdx.y;
    __shared__ float Wt[32][65];
    __shared__ float qsm[32][33];
    int tid = threadIdx.x;
    for (int i = tid; i < 64*32; i += 256) {
        int d = i >> 5, c = i & 31;
        Wt[c][d] = We1[(size_t)d*128 + h*32 + c];
    }
    int n0 = blockIdx.x * 32;
    for (int i = tid; i < 32*32; i += 256) {
        int nn = i >> 5, c = i & 31;
        qsm[nn][c] = (n0+nn < NN) ? g_q1[(size_t)(n0+nn)*128 + h*32 + c] : 0.f;
    }
    __syncthreads();
    int d = tid & 63, nb = tid >> 6;
    #pragma unroll
    for (int p = 0; p < 8; p++) {
        int nn = p*4 + nb;
        float acc = 0.f;
        #pragma unroll
        for (int c = 0; c < 32; c++) acc += qsm[nn][c] * Wt[c][d];
        if (n0+nn < NN) g_t1[(size_t)(n0+nn)*256 + h*64 + d] = acc;
    }
}

__global__ void k_t2(const float* __restrict__ We2) {
    __shared__ float Wt[64][65];
    __shared__ float qsm[32][65];
    int tid = threadIdx.x;
    for (int i = tid; i < 64*64; i += 256) {
        int d = i >> 6, c = i & 63;
        Wt[c][d] = We2[(size_t)d*64 + c];
    }
    int n0 = blockIdx.x * 32;
    for (int i = tid; i < 32*64; i += 256) {
        int nn = i >> 6, c = i & 63;
        qsm[nn][c] = (n0+nn < NN) ? g_q2[(size_t)(n0+nn)*64 + c] : 0.f;
    }
    __syncthreads();
    int d = tid & 63, nb = tid >> 6;
    #pragma unroll
    for (int p = 0; p < 8; p++) {
        int nn = p*4 + nb;
        float acc = 0.f;
        #pragma unroll
        for (int c = 0; c < 64; c++) acc += qsm[nn][c] * Wt[c][d];
        if (n0+nn < NN) g_t2[(size_t)(n0+nn)*64 + d] = acc;
    }
}

// ---------------- attention layer 1 (H=4, C=32) ----------------------------
__global__ void __launch_bounds__(256) k_attn1(const float* __restrict__ ef,
                                               const float* __restrict__ We1) {
    int lane = threadIdx.x & 31;
    int wl   = threadIdx.x >> 5;
    int n    = blockIdx.x*8 + wl;
    __shared__ float smemAll[8*640];
    float* qs = smemAll + wl*640;   // 128 (pre-scaled)
    float* ts = qs + 128;           // 256 (pre-scaled)
    float* gs = qs + 384;           // 256: g[h][64]
    if (n >= NN) return;

    const float inv_s = 0.1767766952966369f;   // 1/sqrt(32)
    {
        float4 q = ((const float4*)(g_q1 + (size_t)n*128))[lane];
        q.x*=inv_s; q.y*=inv_s; q.z*=inv_s; q.w*=inv_s;
        ((float4*)qs)[lane] = q;
        const float4* tsrc = (const float4*)(g_t1 + (size_t)n*256);
        float4 t0 = tsrc[lane], t1 = tsrc[lane+32];
        t0.x*=inv_s; t0.y*=inv_s; t0.z*=inv_s; t0.w*=inv_s;
        t1.x*=inv_s; t1.y*=inv_s; t1.z*=inv_s; t1.w*=inv_s;
        ((float4*)ts)[lane]    = t0;
        ((float4*)ts)[lane+32] = t1;
    }
    __syncwarp();

    u64t accvP[4][2];
    u64t agP[4][4];
    float den[4];
    #pragma unroll
    for (int h = 0; h < 4; h++) {
        accvP[h][0] = 0ull; accvP[h][1] = 0ull;
        agP[h][0] = 0ull; agP[h][1] = 0ull; agP[h][2] = 0ull; agP[h][3] = 0ull;
        den[h] = 0.f;
    }

    int rs = g_rowptr[n], re = g_rowptr[n+1];
    int l8 = lane & 7, grp = lane >> 3;
    const u64t* qU = (const u64t*)qs;
    const u64t* tU = (const u64t*)ts;
    int qo = l8*2;

    for (int base = rs; base < re; base += 32) {
        int cnt = min(32, re - base);
        int2 se = make_int2(0, 0);
        if (lane < cnt) se = g_edges[base + lane];
        #pragma unroll 2
        for (int sub = 0; sub < 8; sub++) {
            int el = sub*4 + grp;
            int esrc = __shfl_sync(FULL, se.x, el);
            int eeid = __shfl_sync(FULL, se.y, el);
            bool valid = el < cnt;
            const ulonglong2* kp = (const ulonglong2*)(g_k1 + (size_t)esrc*128);
            const ulonglong2* ep = (const ulonglong2*)(ef   + (size_t)eeid*64);
            const ulonglong2* vp = (const ulonglong2*)(g_v1 + (size_t)esrc*128);
            ulonglong2 kv0 = kp[l8], kv1 = kp[8+l8], kv2 = kp[16+l8], kv3 = kp[24+l8];
            ulonglong2 ev0 = ldcs2(ep + l8), ev1 = ldcs2(ep + 8 + l8);
            ulonglong2 vv0 = vp[l8], vv1 = vp[8+l8], vv2 = vp[16+l8], vv3 = vp[24+l8];

            u64t aP0 = f2fma(kv0.x, qU[qo],    f2fma(kv0.y, qU[qo+1],    0ull));
            u64t aP1 = f2fma(kv1.x, qU[16+qo], f2fma(kv1.y, qU[16+qo+1], 0ull));
            u64t aP2 = f2fma(kv2.x, qU[32+qo], f2fma(kv2.y, qU[32+qo+1], 0ull));
            u64t aP3 = f2fma(kv3.x, qU[48+qo], f2fma(kv3.y, qU[48+qo+1], 0ull));

            aP0 = f2fma(ev0.x, tU[qo],       aP0); aP0 = f2fma(ev0.y, tU[qo+1],       aP0);
            aP0 = f2fma(ev1.x, tU[16+qo],    aP0); aP0 = f2fma(ev1.y, tU[16+qo+1],    aP0);
            aP1 = f2fma(ev0.x, tU[32+qo],    aP1); aP1 = f2fma(ev0.y, tU[32+qo+1],    aP1);
            aP1 = f2fma(ev1.x, tU[48+qo],    aP1); aP1 = f2fma(ev1.y, tU[48+qo+1],    aP1);
            aP2 = f2fma(ev0.x, tU[64+qo],    aP2); aP2 = f2fma(ev0.y, tU[64+qo+1],    aP2);
            aP2 = f2fma(ev1.x, tU[80+qo],    aP2); aP2 = f2fma(ev1.y, tU[80+qo+1],    aP2);
            aP3 = f2fma(ev0.x, tU[96+qo],    aP3); aP3 = f2fma(ev0.y, tU[96+qo+1],    aP3);
            aP3 = f2fma(ev1.x, tU[112+qo],   aP3); aP3 = f2fma(ev1.y, tU[112+qo+1],   aP3);

            float a0, a1, a2, a3, t;
            upk(aP0, a0, t); a0 += t;
            upk(aP1, a1, t); a1 += t;
            upk(aP2, a2, t); a2 += t;
            upk(aP3, a3, t); a3 += t;
            #pragma unroll
            for (int o = 1; o <= 4; o <<= 1) {
                a0 += __shfl_xor_sync(FULL, a0, o);
                a1 += __shfl_xor_sync(FULL, a1, o);
                a2 += __shfl_xor_sync(FULL, a2, o);
                a3 += __shfl_xor_sync(FULL, a3, o);
            }
            float w0 = valid ? __expf(a0) : 0.f;
            float w1 = valid ? __expf(a1) : 0.f;
            float w2 = valid ? __expf(a2) : 0.f;
            float w3 = valid ? __expf(a3) : 0.f;
            den[0] += w0; den[1] += w1; den[2] += w2; den[3] += w3;
            u64t wP0 = pk(w0,w0), wP1 = pk(w1,w1), wP2 = pk(w2,w2), wP3 = pk(w3,w3);

            accvP[0][0] = f2fma(wP0, vv0.x, accvP[0][0]); accvP[0][1] = f2fma(wP0, vv0.y, accvP[0][1]);
            accvP[1][0] = f2fma(wP1, vv1.x, accvP[1][0]); accvP[1][1] = f2fma(wP1, vv1.y, accvP[1][1]);
            accvP[2][0] = f2fma(wP2, vv2.x, accvP[2][0]); accvP[2][1] = f2fma(wP2, vv2.y, accvP[2][1]);
            accvP[3][0] = f2fma(wP3, vv3.x, accvP[3][0]); accvP[3][1] = f2fma(wP3, vv3.y, accvP[3][1]);

            agP[0][0] = f2fma(wP0, ev0.x, agP[0][0]); agP[0][1] = f2fma(wP0, ev0.y, agP[0][1]);
            agP[0][2] = f2fma(wP0, ev1.x, agP[0][2]); agP[0][3] = f2fma(wP0, ev1.y, agP[0][3]);
            agP[1][0] = f2fma(wP1, ev0.x, agP[1][0]); agP[1][1] = f2fma(wP1, ev0.y, agP[1][1]);
            agP[1][2] = f2fma(wP1, ev1.x, agP[1][2]); agP[1][3] = f2fma(wP1, ev1.y, agP[1][3]);
            agP[2][0] = f2fma(wP2, ev0.x, agP[2][0]); agP[2][1] = f2fma(wP2, ev0.y, agP[2][1]);
            agP[2][2] = f2fma(wP2, ev1.x, agP[2][2]); agP[2][3] = f2fma(wP2, ev1.y, agP[2][3]);
            agP[3][0] = f2fma(wP3, ev0.x, agP[3][0]); agP[3][1] = f2fma(wP3, ev0.y, agP[3][1]);
            agP[3][2] = f2fma(wP3, ev1.x, agP[3][2]); agP[3][3] = f2fma(wP3, ev1.y, agP[3][3]);
        }
    }

    float4 accv[4], aglo[4], aghi[4];
    #pragma unroll
    for (int h = 0; h < 4; h++) {
        upk(accvP[h][0], accv[h].x, accv[h].y); upk(accvP[h][1], accv[h].z, accv[h].w);
        upk(agP[h][0], aglo[h].x, aglo[h].y);   upk(agP[h][1], aglo[h].z, aglo[h].w);
        upk(agP[h][2], aghi[h].x, aghi[h].y);   upk(agP[h][3], aghi[h].z, aghi[h].w);
    }
    #pragma unroll
    for (int o = 8; o <= 16; o <<= 1) {
        #pragma unroll
        for (int h = 0; h < 4; h++) {
            accv[h].x += __shfl_xor_sync(FULL, accv[h].x, o);
            accv[h].y += __shfl_xor_sync(FULL, accv[h].y, o);
            accv[h].z += __shfl_xor_sync(FULL, accv[h].z, o);
            accv[h].w += __shfl_xor_sync(FULL, accv[h].w, o);
            aglo[h].x += __shfl_xor_sync(FULL, aglo[h].x, o);
            aglo[h].y += __shfl_xor_sync(FULL, aglo[h].y, o);
            aglo[h].z += __shfl_xor_sync(FULL, aglo[h].z, o);
            aglo[h].w += __shfl_xor_sync(FULL, aglo[h].w, o);
            aghi[h].x += __shfl_xor_sync(FULL, aghi[h].x, o);
            aghi[h].y += __shfl_xor_sync(FULL, aghi[h].y, o);
            aghi[h].z += __shfl_xor_sync(FULL, aghi[h].z, o);
            aghi[h].w += __shfl_xor_sync(FULL, aghi[h].w, o);
            den[h]    += __shfl_xor_sync(FULL, den[h], o);
        }
    }

    {
        float4 glo = (grp==0)?aglo[0]:((grp==1)?aglo[1]:((grp==2)?aglo[2]:aglo[3]));
        float4 ghi = (grp==0)?aghi[0]:((grp==1)?aghi[1]:((grp==2)?aghi[2]:aghi[3]));
        *(float4*)(gs + grp*64 + l8*4)      = glo;
        *(float4*)(gs + grp*64 + 32 + l8*4) = ghi;
    }
    __syncwarp();

    float denh  = (grp==0)?den[0]:((grp==1)?den[1]:((grp==2)?den[2]:den[3]));
    float4 av   = (grp==0)?accv[0]:((grp==1)?accv[1]:((grp==2)?accv[2]:accv[3]));

    float4 og = make_float4(0.f,0.f,0.f,0.f);
    const float* Wc = We1 + grp*32 + l8*4;
    const float* gh = gs + grp*64;
    #pragma unroll 8
    for (int d = 0; d < 64; d++) {
        float g = gh[d];
        float4 wr = *(const float4*)(Wc + (size_t)d*128);
        og.x += g*wr.x; og.y += g*wr.y; og.z += g*wr.z; og.w += g*wr.w;
    }
    float inv = (denh > 0.f) ? (1.f/denh) : 0.f;
    float4 skip = *(const float4*)(g_h + (size_t)n*128 + lane*4);
    float4 o;
    o.x = fmaxf(fmaf(av.x + og.x, inv, skip.x), 0.f);
    o.y = fmaxf(fmaf(av.y + og.y, inv, skip.y), 0.f);
    o.z = fmaxf(fmaf(av.z + og.z, inv, skip.z), 0.f);
    o.w = fmaxf(fmaf(av.w + og.w, inv, skip.w), 0.f);
    *(float4*)(g_h + (size_t)n*128 + lane*4) = o;
}

// ---------------- attention layer 2 (H=1, C=64) -----------------------------
__global__ void __launch_bounds__(256) k_attn2(const float* __restrict__ ef,
                                               const float* __restrict__ We2,
                                               float* __restrict__ out) {
    int lane = threadIdx.x & 31;
    int wl   = threadIdx.x >> 5;
    int n    = blockIdx.x*8 + wl;
    __shared__ float smemAll[8*256];
    float* qs = smemAll + wl*256;
    float* ts = qs + 64;
    float* gs = qs + 128;
    float* vs = qs + 192;
    if (n >= NN) return;

    {
        float2 q = ((const float2*)(g_q2 + (size_t)n*64))[lane];
        q.x *= 0.125f; q.y *= 0.125f;
        ((float2*)qs)[lane] = q;
        float2 t = ((const float2*)(g_t2 + (size_t)n*64))[lane];
        t.x *= 0.125f; t.y *= 0.125f;
        ((float2*)ts)[lane] = t;
    }
    __syncwarp();

    u64t avP[4] = {0ull,0ull,0ull,0ull};
    u64t agPp[4] = {0ull,0ull,0ull,0ull};
    float den = 0.f;
    int rs = g_rowptr[n], re = g_rowptr[n+1];
    int l8 = lane & 7, grp = lane >> 3;
    const u64t* qU = (const u64t*)qs;
    const u64t* tU = (const u64t*)ts;
    int qo = l8*2;

    for (int base = rs; base < re; base += 32) {
        int cnt = min(32, re - base);
        int2 se = make_int2(0, 0);
        if (lane < cnt) se = g_edges[base + lane];
        #pragma unroll 2
        for (int sub = 0; sub < 8; sub++) {
            int el = sub*4 + grp;
            int esrc = __shfl_sync(FULL, se.x, el);
            int eeid = __shfl_sync(FULL, se.y, el);
            bool valid = el < cnt;
            const ulonglong2* kp = (const ulonglong2*)(g_k2 + (size_t)esrc*64);
            const ulonglong2* ep = (const ulonglong2*)(ef   + (size_t)eeid*64);
            const ulonglong2* vp = (const ulonglong2*)(g_v2 + (size_t)esrc*64);
            ulonglong2 kv0 = kp[l8], kv1 = kp[8+l8];
            ulonglong2 ev0 = ldcs2(ep + l8), ev1 = ldcs2(ep + 8 + l8);
            ulonglong2 vv0 = vp[l8], vv1 = vp[8+l8];

            u64t aP = f2fma(kv0.x, qU[qo],    f2fma(kv0.y, qU[qo+1], 0ull));
            aP = f2fma(kv1.x, qU[16+qo], aP); aP = f2fma(kv1.y, qU[16+qo+1], aP);
            aP = f2fma(ev0.x, tU[qo],    aP); aP = f2fma(ev0.y, tU[qo+1],    aP);
            aP = f2fma(ev1.x, tU[16+qo], aP); aP = f2fma(ev1.y, tU[16+qo+1], aP);
            float a, t2v; upk(aP, a, t2v); a += t2v;
            a += __shfl_xor_sync(FULL, a, 1);
            a += __shfl_xor_sync(FULL, a, 2);
            a += __shfl_xor_sync(FULL, a, 4);
            float w = valid ? __expf(a) : 0.f;
            den += w;
            u64t wP = pk(w, w);
            avP[0] = f2fma(wP, vv0.x, avP[0]); avP[1] = f2fma(wP, vv0.y, avP[1]);
            avP[2] = f2fma(wP, vv1.x, avP[2]); avP[3] = f2fma(wP, vv1.y, avP[3]);
            agPp[0] = f2fma(wP, ev0.x, agPp[0]); agPp[1] = f2fma(wP, ev0.y, agPp[1]);
            agPp[2] = f2fma(wP, ev1.x, agPp[2]); agPp[3] = f2fma(wP, ev1.y, agPp[3]);
        }
    }

    float4 av0, av1, ag0, ag1;
    upk(avP[0], av0.x, av0.y); upk(avP[1], av0.z, av0.w);
    upk(avP[2], av1.x, av1.y); upk(avP[3], av1.z, av1.w);
    upk(agPp[0], ag0.x, ag0.y); upk(agPp[1], ag0.z, ag0.w);
    upk(agPp[2], ag1.x, ag1.y); upk(agPp[3], ag1.z, ag1.w);

    #pragma unroll
    for (int o = 8; o <= 16; o <<= 1) {
        av0.x += __shfl_xor_sync(FULL, av0.x, o); av0.y += __shfl_xor_sync(FULL, av0.y, o);
        av0.z += __shfl_xor_sync(FULL, av0.z, o); av0.w += __shfl_xor_sync(FULL, av0.w, o);
        av1.x += __shfl_xor_sync(FULL, av1.x, o); av1.y += __shfl_xor_sync(FULL, av1.y, o);
        av1.z += __shfl_xor_sync(FULL, av1.z, o); av1.w += __shfl_xor_sync(FULL, av1.w, o);
        ag0.x += __shfl_xor_sync(FULL, ag0.x, o); ag0.y += __shfl_xor_sync(FULL, ag0.y, o);
        ag0.z += __shfl_xor_sync(FULL, ag0.z, o); ag0.w += __shfl_xor_sync(FULL, ag0.w, o);
        ag1.x += __shfl_xor_sync(FULL, ag1.x, o); ag1.y += __shfl_xor_sync(FULL, ag1.y, o);
        ag1.z += __shfl_xor_sync(FULL, ag1.z, o); ag1.w += __shfl_xor_sync(FULL, ag1.w, o);
        den   += __shfl_xor_sync(FULL, den, o);
    }

    if (grp == 0) {
        *(float4*)(gs + l8*4)      = ag0;
        *(float4*)(gs + 32 + l8*4) = ag1;
        *(float4*)(vs + l8*4)      = av0;
        *(float4*)(vs + 32 + l8*4) = av1;
    }
    __syncwarp();

    float2 og = make_float2(0.f,0.f);
    const float* Wc = We2 + lane*2;
    #pragma unroll 8
    for (int d = 0; d < 64; d++) {
        float g = gs[d];
        float2 wr = *(const float2*)(Wc + (size_t)d*64);
        og.x += g*wr.x; og.y += g*wr.y;
    }
    float inv = (den > 0.f) ? (1.f/den) : 0.f;
    float2 s2 = *(const float2*)(g_s2 + (size_t)n*64 + lane*2);
    float2 o;
    o.x = fmaf(vs[lane*2]   + og.x, inv, s2.x);
    o.y = fmaf(vs[lane*2+1] + og.y, inv, s2.y);
    *(float2*)(out + (size_t)n*64 + lane*2) = o;
}

// ---------------- launch -----------------------------------------------------
extern "C" void kernel_launch(void* const* d_in, const int* in_sizes, int n_in,
                              void* d_out, int out_size)
{
    const float* x   = (const float*)d_in[0];
    const float* ef  = (const float*)d_in[1];
    const int*   ei  = (const int*)  d_in[2];
    const float *Wq1 = (const float*)d_in[3],  *bq1 = (const float*)d_in[4];
    const float *Wk1 = (const float*)d_in[5],  *bk1 = (const float*)d_in[6];
    const float *Wv1 = (const float*)d_in[7],  *bv1 = (const float*)d_in[8];
    const float *We1 = (const float*)d_in[9];
    const float *Ws1 = (const float*)d_in[10], *bs1 = (const float*)d_in[11];
    const float *Wq2 = (const float*)d_in[12], *bq2 = (const float*)d_in[13];
    const float *Wk2 = (const float*)d_in[14], *bk2 = (const float*)d_in[15];
    const float *Wv2 = (const float*)d_in[16], *bv2 = (const float*)d_in[17];
    const float *We2 = (const float*)d_in[18];
    const float *Ws2 = (const float*)d_in[19], *bs2 = (const float*)d_in[20];
    float* out = (float*)d_out;

    const int* srcp = ei;        // edge_index[0]
    const int* dstp = ei + EE;   // edge_index[1]

    k_zero_cnt<<<(NN+255)/256, 256>>>();
    k_hist   <<<(EE+255)/256, 256>>>(dstp);
    k_scan   <<<1, 1024>>>();
    dim3 g1((NN+63)/64, 4);
    k_node1<<<g1, 256>>>(x, Wq1,bq1, Wk1,bk1, Wv1,bv1, Ws1,bs1);
    k_scatter<<<(EE+255)/256, 256>>>(srcp, dstp);

    dim3 gt1((NN+31)/32, 4);
    k_t1   <<<gt1, 256>>>(We1);
    k_attn1<<<(NN+7)/8, 256>>>(ef, We1);

    dim3 g2((NN+127)/128, 4);
    k_node2<<<g2, 256>>>(Wq2,bq2, Wk2,bk2, Wv2,bv2, Ws2,bs2);
    k_t2   <<<(NN+31)/32, 256>>>(We2);
    k_attn2<<<(NN+7)/8, 256>>>(ef, We2, out);
}

// round 6
// speedup vs baseline: 1.0983x; 1.0983x over previous
#include <cuda_runtime.h>

#define NN 50000
#define EE 1600000
#define FULL 0xffffffffu

typedef unsigned long long u64t;

__device__ __forceinline__ u64t pk(float lo, float hi) {
    u64t r; asm("mov.b64 %0,{%1,%2};" : "=l"(r) : "f"(lo), "f"(hi)); return r;
}
__device__ __forceinline__ void upk(u64t v, float& lo, float& hi) {
    asm("mov.b64 {%0,%1},%2;" : "=f"(lo), "=f"(hi) : "l"(v));
}
__device__ __forceinline__ u64t f2fma(u64t a, u64t b, u64t c) {
    u64t d; asm("fma.rn.f32x2 %0,%1,%2,%3;" : "=l"(d) : "l"(a), "l"(b), "l"(c)); return d;
}
// streaming (evict-first) 16B load — keeps ef out of L2 so node tables stay resident
__device__ __forceinline__ ulonglong2 ldcs2(const ulonglong2* p) {
    ulonglong2 r;
    asm("ld.global.cs.v2.u64 {%0,%1},[%2];" : "=l"(r.x), "=l"(r.y) : "l"(p));
    return r;
}

// ---------------- scratch (device globals; no allocation allowed) ----------
__device__ float g_q1[NN*128];
__device__ float g_k1[NN*128];
__device__ float g_v1[NN*128];
__device__ float g_h [NN*128];
__device__ float g_t1[NN*256];
__device__ float g_q2[NN*64];
__device__ float g_k2[NN*64];
__device__ float g_v2[NN*64];
__device__ float g_s2[NN*64];
__device__ float g_t2[NN*64];
__device__ int   g_cnt[NN];
__device__ int   g_rowptr[NN+1];
__device__ int   g_woff[NN];
__device__ int   g_bsum[64];
__device__ int2  g_edges[EE];

// ---------------- CSR build ------------------------------------------------
__global__ void k_zero_cnt() {
    int i = blockIdx.x*blockDim.x + threadIdx.x;
    if (i < NN) g_cnt[i] = 0;
}

__global__ void k_hist(const int* __restrict__ dst) {
    int e = blockIdx.x*blockDim.x + threadIdx.x;
    if (e < EE) atomicAdd(&g_cnt[dst[e]], 1);
}

// multi-block scan: A = per-block local exclusive scan, B = scan of block sums,
// C = add block offsets
__global__ void k_scanA() {
    __shared__ int s[1024];
    int b = blockIdx.x;
    int i = b*1024 + threadIdx.x;
    int v = (i < NN) ? g_cnt[i] : 0;
    s[threadIdx.x] = v;
    __syncthreads();
    for (int off = 1; off < 1024; off <<= 1) {
        int t = (threadIdx.x >= off) ? s[threadIdx.x - off] : 0;
        __syncthreads();
        s[threadIdx.x] += t;
        __syncthreads();
    }
    if (i < NN) g_rowptr[i] = s[threadIdx.x] - v;
    if (threadIdx.x == 1023) g_bsum[b] = s[1023];
}

__global__ void k_scanB() {
    __shared__ int s[64];
    int t = threadIdx.x;
    int v = (t < 49) ? g_bsum[t] : 0;
    s[t] = v;
    __syncthreads();
    for (int off = 1; off < 64; off <<= 1) {
        int x = (t >= off) ? s[t - off] : 0;
        __syncthreads();
        s[t] += x;
        __syncthreads();
    }
    if (t < 49) g_bsum[t] = s[t] - v;
    if (t == 48) g_rowptr[NN] = s[48];
}

__global__ void k_scanC() {
    int i = blockIdx.x*blockDim.x + threadIdx.x;
    if (i < NN) {
        int r = g_rowptr[i] + g_bsum[i >> 10];
        g_rowptr[i] = r;
        g_woff[i] = r;
    }
}

__global__ void k_scatter(const int* __restrict__ src, const int* __restrict__ dst) {
    int e = blockIdx.x*blockDim.x + threadIdx.x;
    if (e < EE) {
        int d = dst[e];
        int p = atomicAdd(&g_woff[d], 1);
        g_edges[p] = make_int2(src[e], e);
    }
}

// ---------------- node linear layers (R4 versions: known-good) -------------
__global__ void k_node1(const float* __restrict__ x,
    const float* __restrict__ Wq, const float* __restrict__ bq,
    const float* __restrict__ Wk, const float* __restrict__ bk,
    const float* __restrict__ Wv, const float* __restrict__ bv,
    const float* __restrict__ Ws, const float* __restrict__ bs)
{
    const int CIN = 128, COUT = 128, BN = 16;
    int mat = blockIdx.y;
    const float* W = (mat==0)?Wq:((mat==1)?Wk:((mat==2)?Wv:Ws));
    const float* b = (mat==0)?bq:((mat==1)?bk:((mat==2)?bv:bs));
    float* o = (mat==0)?g_q1:((mat==1)?g_k1:((mat==2)?g_v1:g_h));
    int n0 = blockIdx.x * BN;

    __shared__ float xs[CIN][BN];
    for (int i = threadIdx.x; i < BN*CIN; i += COUT) {
        int nn = i / CIN, c = i % CIN;
        xs[c][nn] = x[(size_t)(n0+nn)*CIN + c];
    }
    __syncthreads();

    int col = threadIdx.x;
    float bb = b[col];
    u64t accP[8];
    u64t bbP = pk(bb, bb);
    #pragma unroll
    for (int j = 0; j < 8; j++) accP[j] = bbP;

    #pragma unroll 2
    for (int k = 0; k < CIN; k++) {
        float wv = W[(size_t)k*COUT + col];
        u64t wvP = pk(wv, wv);
        const u64t* xr = (const u64t*)xs[k];
        #pragma unroll
        for (int j = 0; j < 8; j++) accP[j] = f2fma(wvP, xr[j], accP[j]);
    }
    #pragma unroll
    for (int j = 0; j < 8; j++) {
        float a0, a1; upk(accP[j], a0, a1);
        o[(size_t)(n0+2*j)*COUT + col]   = a0;
        o[(size_t)(n0+2*j+1)*COUT + col] = a1;
    }
}

__global__ void k_node2(
    const float* __restrict__ Wq, const float* __restrict__ bq,
    const float* __restrict__ Wk, const float* __restrict__ bk,
    const float* __restrict__ Wv, const float* __restrict__ bv,
    const float* __restrict__ Ws, const float* __restrict__ bs)
{
    const int CIN = 128, COUT = 64, BN = 16;
    int mat = blockIdx.y;
    const float* W = (mat==0)?Wq:((mat==1)?Wk:((mat==2)?Wv:Ws));
    const float* b = (mat==0)?bq:((mat==1)?bk:((mat==2)?bv:bs));
    float* o = (mat==0)?g_q2:((mat==1)?g_k2:((mat==2)?g_v2:g_s2));
    int n0 = blockIdx.x * BN;

    __shared__ float xs[CIN][BN];
    for (int i = threadIdx.x; i < BN*CIN; i += COUT) {
        int nn = i / CIN, c = i % CIN;
        xs[c][nn] = g_h[(size_t)(n0+nn)*CIN + c];
    }
    __syncthreads();

    int col = threadIdx.x;
    float bb = b[col];
    u64t accP[8];
    u64t bbP = pk(bb, bb);
    #pragma unroll
    for (int j = 0; j < 8; j++) accP[j] = bbP;

    #pragma unroll 2
    for (int k = 0; k < CIN; k++) {
        float wv = W[(size_t)k*COUT + col];
        u64t wvP = pk(wv, wv);
        const u64t* xr = (const u64t*)xs[k];
        #pragma unroll
        for (int j = 0; j < 8; j++) accP[j] = f2fma(wvP, xr[j], accP[j]);
    }
    #pragma unroll
    for (int j = 0; j < 8; j++) {
        float a0, a1; upk(accP[j], a0, a1);
        o[(size_t)(n0+2*j)*COUT + col]   = a0;
        o[(size_t)(n0+2*j+1)*COUT + col] = a1;
    }
}

// ---------------- t tables --------------------------------------------------
__global__ void k_t1(const float* __restrict__ We1) {
    int h = blockIdx.y;
    __shared__ float Wt[32][65];
    __shared__ float qsm[32][33];
    int tid = threadIdx.x;
    for (int i = tid; i < 64*32; i += 256) {
        int d = i >> 5, c = i & 31;
        Wt[c][d] = We1[(size_t)d*128 + h*32 + c];
    }
    int n0 = blockIdx.x * 32;
    for (int i = tid; i < 32*32; i += 256) {
        int nn = i >> 5, c = i & 31;
        qsm[nn][c] = (n0+nn < NN) ? g_q1[(size_t)(n0+nn)*128 + h*32 + c] : 0.f;
    }
    __syncthreads();
    int d = tid & 63, nb = tid >> 6;
    #pragma unroll
    for (int p = 0; p < 8; p++) {
        int nn = p*4 + nb;
        float acc = 0.f;
        #pragma unroll
        for (int c = 0; c < 32; c++) acc += qsm[nn][c] * Wt[c][d];
        if (n0+nn < NN) g_t1[(size_t)(n0+nn)*256 + h*64 + d] = acc;
    }
}

__global__ void k_t2(const float* __restrict__ We2) {
    __shared__ float Wt[64][65];
    __shared__ float qsm[32][65];
    int tid = threadIdx.x;
    for (int i = tid; i < 64*64; i += 256) {
        int d = i >> 6, c = i & 63;
        Wt[c][d] = We2[(size_t)d*64 + c];
    }
    int n0 = blockIdx.x * 32;
    for (int i = tid; i < 32*64; i += 256) {
        int nn = i >> 6, c = i & 63;
        qsm[nn][c] = (n0+nn < NN) ? g_q2[(size_t)(n0+nn)*64 + c] : 0.f;
    }
    __syncthreads();
    int d = tid & 63, nb = tid >> 6;
    #pragma unroll
    for (int p = 0; p < 8; p++) {
        int nn = p*4 + nb;
        float acc = 0.f;
        #pragma unroll
        for (int c = 0; c < 64; c++) acc += qsm[nn][c] * Wt[c][d];
        if (n0+nn < NN) g_t2[(size_t)(n0+nn)*64 + d] = acc;
    }
}

// ---------------- attention layer 1 (H=4, C=32): 2-phase, ownership layout --
// lane owns: head grp=lane>>3; v/out channels lane*4..+3; g channels l8*8..+7
__global__ void __launch_bounds__(256) k_attn1(const float* __restrict__ ef,
                                               const float* __restrict__ We1) {
    int lane = threadIdx.x & 31;
    int wl   = threadIdx.x >> 5;
    int n    = blockIdx.x*8 + wl;
    __shared__ float smemAll[8*512];
    float* qs  = smemAll + wl*512;   // 128 (pre-scaled)
    float* ts  = qs + 128;           // 256 (pre-scaled; reused as g in epilogue)
    float* aux = qs + 384;           // 128: w[32 edges][4 heads]
    if (n >= NN) return;

    const float inv_s = 0.1767766952966369f;   // 1/sqrt(32)
    {
        float4 q = ((const float4*)(g_q1 + (size_t)n*128))[lane];
        q.x*=inv_s; q.y*=inv_s; q.z*=inv_s; q.w*=inv_s;
        ((float4*)qs)[lane] = q;
        const float4* tsrc = (const float4*)(g_t1 + (size_t)n*256);
        float4 t0 = tsrc[lane], t1 = tsrc[lane+32];
        t0.x*=inv_s; t0.y*=inv_s; t0.z*=inv_s; t0.w*=inv_s;
        t1.x*=inv_s; t1.y*=inv_s; t1.z*=inv_s; t1.w*=inv_s;
        ((float4*)ts)[lane]    = t0;
        ((float4*)ts)[lane+32] = t1;
    }
    __syncwarp();

    u64t accv0=0ull, accv1=0ull;               // v channels lane*4..+3
    u64t ag0=0ull, ag1=0ull, ag2=0ull, ag3=0ull; // g[grp][l8*8..+7]
    float den = 0.f;

    int rs = g_rowptr[n], re = g_rowptr[n+1];
    int l8 = lane & 7, grp = lane >> 3;
    const u64t* qU = (const u64t*)qs;
    const u64t* tU = (const u64t*)ts;
    int qo = l8*2;

    for (int base = rs; base < re; base += 32) {
        int cnt = min(32, re - base);
        int2 se = make_int2(0, 0);
        if (lane < cnt) se = g_edges[base + lane];
        // ---- phase 1: weights for 32 edges (8 lanes cooperate per edge) ----
        #pragma unroll 2
        for (int sub = 0; sub < 8; sub++) {
            int el = sub*4 + grp;
            int esrc = __shfl_sync(FULL, se.x, el);
            int eeid = __shfl_sync(FULL, se.y, el);
            bool valid = el < cnt;
            const ulonglong2* kp = (const ulonglong2*)(g_k1 + (size_t)esrc*128);
            const ulonglong2* ep = (const ulonglong2*)(ef   + (size_t)eeid*64);
            ulonglong2 kv0 = kp[l8], kv1 = kp[8+l8], kv2 = kp[16+l8], kv3 = kp[24+l8];
            ulonglong2 ev0 = ldcs2(ep + l8), ev1 = ldcs2(ep + 8 + l8);

            u64t aP0 = f2fma(kv0.x, qU[qo],    f2fma(kv0.y, qU[qo+1],    0ull));
            u64t aP1 = f2fma(kv1.x, qU[16+qo], f2fma(kv1.y, qU[16+qo+1], 0ull));
            u64t aP2 = f2fma(kv2.x, qU[32+qo], f2fma(kv2.y, qU[32+qo+1], 0ull));
            u64t aP3 = f2fma(kv3.x, qU[48+qo], f2fma(kv3.y, qU[48+qo+1], 0ull));

            aP0 = f2fma(ev0.x, tU[qo],       aP0); aP0 = f2fma(ev0.y, tU[qo+1],       aP0);
            aP0 = f2fma(ev1.x, tU[16+qo],    aP0); aP0 = f2fma(ev1.y, tU[16+qo+1],    aP0);
            aP1 = f2fma(ev0.x, tU[32+qo],    aP1); aP1 = f2fma(ev0.y, tU[32+qo+1],    aP1);
            aP1 = f2fma(ev1.x, tU[48+qo],    aP1); aP1 = f2fma(ev1.y, tU[48+qo+1],    aP1);
            aP2 = f2fma(ev0.x, tU[64+qo],    aP2); aP2 = f2fma(ev0.y, tU[64+qo+1],    aP2);
            aP2 = f2fma(ev1.x, tU[80+qo],    aP2); aP2 = f2fma(ev1.y, tU[80+qo+1],    aP2);
            aP3 = f2fma(ev0.x, tU[96+qo],    aP3); aP3 = f2fma(ev0.y, tU[96+qo+1],    aP3);
            aP3 = f2fma(ev1.x, tU[112+qo],   aP3); aP3 = f2fma(ev1.y, tU[112+qo+1],   aP3);

            float a0, a1, a2, a3, t;
            upk(aP0, a0, t); a0 += t;
            upk(aP1, a1, t); a1 += t;
            upk(aP2, a2, t); a2 += t;
            upk(aP3, a3, t); a3 += t;
            #pragma unroll
            for (int o = 1; o <= 4; o <<= 1) {
                a0 += __shfl_xor_sync(FULL, a0, o);
                a1 += __shfl_xor_sync(FULL, a1, o);
                a2 += __shfl_xor_sync(FULL, a2, o);
                a3 += __shfl_xor_sync(FULL, a3, o);
            }
            if (l8 == 0) {
                float4 w4;
                w4.x = valid ? __expf(a0) : 0.f;
                w4.y = valid ? __expf(a1) : 0.f;
                w4.z = valid ? __expf(a2) : 0.f;
                w4.w = valid ? __expf(a3) : 0.f;
                *(float4*)(aux + el*4) = w4;
            }
        }
        __syncwarp();
        // ---- phase 2: accumulate (whole-warp coalesced rows, no reduces) ---
        #pragma unroll 4
        for (int e = 0; e < cnt; e++) {
            int esrc = __shfl_sync(FULL, se.x, e);
            int eeid = __shfl_sync(FULL, se.y, e);
            float w = aux[e*4 + grp];
            den += w;
            u64t wP = pk(w, w);
            ulonglong2 vv = ((const ulonglong2*)(g_v1 + (size_t)esrc*128))[lane];
            accv0 = f2fma(wP, vv.x, accv0);
            accv1 = f2fma(wP, vv.y, accv1);
            const ulonglong2* ep2 = (const ulonglong2*)(ef + (size_t)eeid*64);
            ulonglong2 e0 = ep2[l8*2], e1 = ep2[l8*2+1];
            ag0 = f2fma(wP, e0.x, ag0); ag1 = f2fma(wP, e0.y, ag1);
            ag2 = f2fma(wP, e1.x, ag2); ag3 = f2fma(wP, e1.y, ag3);
        }
        __syncwarp();
    }

    // ---- epilogue: write g to smem (ts reused), then We1 GEMM --------------
    __syncwarp();
    u64t* gsU = (u64t*)ts;
    gsU[grp*32 + l8*4 + 0] = ag0;
    gsU[grp*32 + l8*4 + 1] = ag1;
    gsU[grp*32 + l8*4 + 2] = ag2;
    gsU[grp*32 + l8*4 + 3] = ag3;
    __syncwarp();

    float4 og = make_float4(0.f,0.f,0.f,0.f);
    const float* Wc = We1 + grp*32 + l8*4;
    const float* gh = ts + grp*64;
    #pragma unroll 8
    for (int d = 0; d < 64; d++) {
        float g = gh[d];
        float4 wr = *(const float4*)(Wc + (size_t)d*128);
        og.x += g*wr.x; og.y += g*wr.y; og.z += g*wr.z; og.w += g*wr.w;
    }
    float inv = (den > 0.f) ? (1.f/den) : 0.f;
    float4 av; upk(accv0, av.x, av.y); upk(accv1, av.z, av.w);
    float4 skip = *(const float4*)(g_h + (size_t)n*128 + lane*4);
    float4 o;
    o.x = fmaxf(fmaf(av.x + og.x, inv, skip.x), 0.f);
    o.y = fmaxf(fmaf(av.y + og.y, inv, skip.y), 0.f);
    o.z = fmaxf(fmaf(av.z + og.z, inv, skip.z), 0.f);
    o.w = fmaxf(fmaf(av.w + og.w, inv, skip.w), 0.f);
    *(float4*)(g_h + (size_t)n*128 + lane*4) = o;
}

// ---------------- attention layer 2 (H=1, C=64): 2-phase, ownership layout --
__global__ void __launch_bounds__(256) k_attn2(const float* __restrict__ ef,
                                               const float* __restrict__ We2,
                                               float* __restrict__ out) {
    int lane = threadIdx.x & 31;
    int wl   = threadIdx.x >> 5;
    int n    = blockIdx.x*8 + wl;
    __shared__ float smemAll[8*160];
    float* qs  = smemAll + wl*160;  // 64 (pre-scaled)
    float* ts  = qs + 64;           // 64 (pre-scaled; reused as g in epilogue)
    float* aux = qs + 128;          // 32: w per edge
    if (n >= NN) return;

    {
        float2 q = ((const float2*)(g_q2 + (size_t)n*64))[lane];
        q.x *= 0.125f; q.y *= 0.125f;
        ((float2*)qs)[lane] = q;
        float2 t = ((const float2*)(g_t2 + (size_t)n*64))[lane];
        t.x *= 0.125f; t.y *= 0.125f;
        ((float2*)ts)[lane] = t;
    }
    __syncwarp();

    u64t accv = 0ull;   // v channels lane*2..+1
    u64t ag   = 0ull;   // g channels lane*2..+1
    float den = 0.f;
    int rs = g_rowptr[n], re = g_rowptr[n+1];
    int l8 = lane & 7, grp = lane >> 3;
    const u64t* qU = (const u64t*)qs;
    const u64t* tU = (const u64t*)ts;
    int qo = l8*2;

    for (int base = rs; base < re; base += 32) {
        int cnt = min(32, re - base);
        int2 se = make_int2(0, 0);
        if (lane < cnt) se = g_edges[base + lane];
        // phase 1: weights
        #pragma unroll 2
        for (int sub = 0; sub < 8; sub++) {
            int el = sub*4 + grp;
            int esrc = __shfl_sync(FULL, se.x, el);
            int eeid = __shfl_sync(FULL, se.y, el);
            bool valid = el < cnt;
            const ulonglong2* kp = (const ulonglong2*)(g_k2 + (size_t)esrc*64);
            const ulonglong2* ep = (const ulonglong2*)(ef   + (size_t)eeid*64);
            ulonglong2 kv0 = kp[l8], kv1 = kp[8+l8];
            ulonglong2 ev0 = ldcs2(ep + l8), ev1 = ldcs2(ep + 8 + l8);

            u64t aP = f2fma(kv0.x, qU[qo],    f2fma(kv0.y, qU[qo+1], 0ull));
            aP = f2fma(kv1.x, qU[16+qo], aP); aP = f2fma(kv1.y, qU[16+qo+1], aP);
            aP = f2fma(ev0.x, tU[qo],    aP); aP = f2fma(ev0.y, tU[qo+1],    aP);
            aP = f2fma(ev1.x, tU[16+qo], aP); aP = f2fma(ev1.y, tU[16+qo+1], aP);
            float a, t2v; upk(aP, a, t2v); a += t2v;
            a += __shfl_xor_sync(FULL, a, 1);
            a += __shfl_xor_sync(FULL, a, 2);
            a += __shfl_xor_sync(FULL, a, 4);
            if (l8 == 0) aux[el] = valid ? __expf(a) : 0.f;
        }
        __syncwarp();
        // phase 2: accumulate
        #pragma unroll 4
        for (int e = 0; e < cnt; e++) {
            int esrc = __shfl_sync(FULL, se.x, e);
            int eeid = __shfl_sync(FULL, se.y, e);
            float w = aux[e];
            den += w;
            u64t wP = pk(w, w);
            u64t vv = ((const u64t*)(g_v2 + (size_t)esrc*64))[lane];
            accv = f2fma(wP, vv, accv);
            u64t eg = ((const u64t*)(ef + (size_t)eeid*64))[lane];
            ag = f2fma(wP, eg, ag);
        }
        __syncwarp();
    }

    // epilogue
    __syncwarp();
    ((u64t*)ts)[lane] = ag;
    __syncwarp();

    float2 og = make_float2(0.f,0.f);
    const float* Wc = We2 + lane*2;
    #pragma unroll 8
    for (int d = 0; d < 64; d++) {
        float g = ts[d];
        float2 wr = *(const float2*)(Wc + (size_t)d*64);
        og.x += g*wr.x; og.y += g*wr.y;
    }
    float inv = (den > 0.f) ? (1.f/den) : 0.f;
    float2 av; upk(accv, av.x, av.y);
    float2 s2 = *(const float2*)(g_s2 + (size_t)n*64 + lane*2);
    float2 o;
    o.x = fmaf(av.x + og.x, inv, s2.x);
    o.y = fmaf(av.y + og.y, inv, s2.y);
    *(float2*)(out + (size_t)n*64 + lane*2) = o;
}

// ---------------- launch -----------------------------------------------------
extern "C" void kernel_launch(void* const* d_in, const int* in_sizes, int n_in,
                              void* d_out, int out_size)
{
    const float* x   = (const float*)d_in[0];
    const float* ef  = (const float*)d_in[1];
    const int*   ei  = (const int*)  d_in[2];
    const float *Wq1 = (const float*)d_in[3],  *bq1 = (const float*)d_in[4];
    const float *Wk1 = (const float*)d_in[5],  *bk1 = (const float*)d_in[6];
    const float *Wv1 = (const float*)d_in[7],  *bv1 = (const float*)d_in[8];
    const float *We1 = (const float*)d_in[9];
    const float *Ws1 = (const float*)d_in[10], *bs1 = (const float*)d_in[11];
    const float *Wq2 = (const float*)d_in[12], *bq2 = (const float*)d_in[13];
    const float *Wk2 = (const float*)d_in[14], *bk2 = (const float*)d_in[15];
    const float *Wv2 = (const float*)d_in[16], *bv2 = (const float*)d_in[17];
    const float *We2 = (const float*)d_in[18];
    const float *Ws2 = (const float*)d_in[19], *bs2 = (const float*)d_in[20];
    float* out = (float*)d_out;

    const int* srcp = ei;        // edge_index[0]
    const int* dstp = ei + EE;   // edge_index[1]

    k_zero_cnt<<<(NN+255)/256, 256>>>();
    k_hist    <<<(EE+255)/256, 256>>>(dstp);
    k_scanA   <<<49, 1024>>>();
    dim3 g1(NN/16, 4);
    k_node1   <<<g1, 128>>>(x, Wq1,bq1, Wk1,bk1, Wv1,bv1, Ws1,bs1);   // profiled slot
    k_scanB   <<<1, 64>>>();
    k_scanC   <<<(NN+255)/256, 256>>>();
    k_scatter <<<(EE+255)/256, 256>>>(srcp, dstp);

    dim3 gt1((NN+31)/32, 4);
    k_t1   <<<gt1, 256>>>(We1);
    k_attn1<<<(NN+7)/8, 256>>>(ef, We1);

    k_node2<<<g1, 64>>>(Wq2,bq2, Wk2,bk2, Wv2,bv2, Ws2,bs2);
    k_t2   <<<(NN+31)/32, 256>>>(We2);
    k_attn2<<<(NN+7)/8, 256>>>(ef, We2, out);
}